// round 13
// baseline (speedup 1.0000x reference)
#include <cuda_runtime.h>
#include <math.h>

#define NB 128
#define NP 8732
#define NM 16
#define NC 21
#define TBLK 128
#define NTIL 69           // ceil(8732/128)

// ---------------- scratch (self-cleaning; static zero-init for first run) ----------------
__device__ float    g_confneg[NB * NP];    // conf0 = lse - sv[0] (K1 CE rewrites fully)
__device__ unsigned g_pack[NB * NP];       // (bestv bits & ~0xF) | bestm (K1 match rewrites fully)
__device__ unsigned long long g_best[NB * NM];
__device__ int    g_npos[NB];
__device__ int    g_npos_total;
__device__ double g_loc_sum;
__device__ double g_pos_sum;
__device__ double g_hard_sum;
__device__ int    g_done;

// ---------------- PDL helpers ----------------
__device__ __forceinline__ void pdl_wait() {
    asm volatile("griddepcontrol.wait;" ::: "memory");
}
__device__ __forceinline__ void pdl_trigger() {
    asm volatile("griddepcontrol.launch_dependents;" ::: "memory");
}

// ---------------- numeric helpers ----------------
__device__ __forceinline__ float ce_lse(const float* sv) {
    float mx = sv[0];
    #pragma unroll
    for (int c = 1; c < NC; c++) mx = fmaxf(mx, sv[c]);
    float se = 0.0f;
    #pragma unroll
    for (int c = 0; c < NC; c++) se += __expf(sv[c] - mx);
    return __logf(se) + mx;
}

__device__ __forceinline__ float loc_l1(float4 bx, float4 pr, float4 pl) {
    float cx = 0.5f * (bx.x + bx.z);
    float cy = 0.5f * (bx.y + bx.w);
    float cw = bx.z - bx.x;
    float ch = bx.w - bx.y;
    float g0 = (cx - pr.x) * 10.0f / pr.z;
    float g1 = (cy - pr.y) * 10.0f / pr.w;
    float g2 = __logf(cw / pr.z) * 5.0f;
    float g3 = __logf(ch / pr.w) * 5.0f;
    return fabsf(pl.x - g0) + fabsf(pl.y - g1) + fabsf(pl.z - g2) + fabsf(pl.w - g3);
}

// ================= K1: block-specialized CE (x<69) + match+positives (x>=69) =================
__global__ void __launch_bounds__(TBLK) k1_kernel(
        const float4* __restrict__ plocs,
        const float*  __restrict__ scores,
        const float4* __restrict__ boxes,
        const int*    __restrict__ labels,
        const float4* __restrict__ priors) {
    __shared__ float ssc[TBLK * NC];              // CE branch (10.75 KB)
    __shared__ float4 sbox[NM];                   // match branch
    __shared__ float  sarea[NM];
    __shared__ int    slab[NM];
    __shared__ unsigned long long swarp[NM][4];
    __shared__ float  rl[4], rp[4];
    __shared__ int    rc[4];

    int b = blockIdx.y;
    int tid = threadIdx.x;
    int lane = tid & 31, warp = tid >> 5;

    if (blockIdx.x < NTIL) {
        // ---------------- CE branch: conf0 = lse - sv[0] for 128 priors ----------------
        int base = blockIdx.x * TBLK;
        int nval = NP - base; if (nval > TBLK) nval = TBLK;
        const float4* src = (const float4*)(scores + ((size_t)b * NP + base) * NC);
        int nvec = (nval * NC) >> 2;              // (nval*21) % 4 == 0, base 16B-aligned
        for (int i = tid; i < nvec; i += TBLK) {
            unsigned sa = (unsigned)__cvta_generic_to_shared(&((float4*)ssc)[i]);
            asm volatile("cp.async.cg.shared.global [%0], [%1], 16;" :: "r"(sa), "l"(src + i));
        }
        asm volatile("cp.async.commit_group;");
        asm volatile("cp.async.wait_group 0;");
        __syncthreads();
        if (tid < nval) {
            const float* sv = ssc + tid * NC;     // stride 21: conflict-free
            g_confneg[b * NP + base + tid] = ce_lse(sv) - sv[0];
        }
        __syncthreads();
        pdl_trigger();
    } else {
        // ------- match branch: IoUs, per-prior best, per-object argmax, positive CE/loc -------
        int base = (blockIdx.x - NTIL) * TBLK;
        int nval = NP - base; if (nval > TBLK) nval = TBLK;

        if (tid < NM) {
            float4 bx = __ldg(&boxes[b * NM + tid]);
            sbox[tid] = bx;
            sarea[tid] = (bx.z - bx.x) * (bx.w - bx.y);
            slab[tid] = labels[b * NM + tid];
        }
        if (tid < NM * 4) ((unsigned long long*)swarp)[tid] = 0ull;
        __syncthreads();

        int p = base + tid;
        bool valid = (tid < nval);
        unsigned vmask = __ballot_sync(0xFFFFFFFFu, valid);

        float bestv = -1.0f;
        int   bestm = 0;
        float4 pr = make_float4(0.f, 0.f, 1.f, 1.f);
        if (valid) pr = __ldg(&priors[p]);
        {
            float px1 = pr.x - 0.5f * pr.z;
            float py1 = pr.y - 0.5f * pr.w;
            float px2 = pr.x + 0.5f * pr.z;
            float py2 = pr.y + 0.5f * pr.w;
            float pa  = pr.z * pr.w;
            #pragma unroll
            for (int m = 0; m < NM; m++) {
                float iou = 0.0f;
                if (valid) {
                    float4 bx = sbox[m];
                    float lx = fmaxf(bx.x, px1), ly = fmaxf(bx.y, py1);
                    float rx = fminf(bx.z, px2), ry = fminf(bx.w, py2);
                    float w = fmaxf(rx - lx, 0.0f), h = fmaxf(ry - ly, 0.0f);
                    float inter = w * h;
                    iou = __fdividef(inter, sarea[m] + pa - inter);
                }
                if (iou > bestv) { bestv = iou; bestm = m; }  // strict >: lowest m on ties

                // warp argmax over p: REDUX + ballot; winner = lowest lane = lowest p
                unsigned key = valid ? __float_as_uint(iou) : 0u;
                unsigned wmax = __reduce_max_sync(0xFFFFFFFFu, key);
                unsigned ball = __ballot_sync(0xFFFFFFFFu, key == wmax) & vmask;
                if (ball && lane == (int)(__ffs(ball) - 1))
                    swarp[m][warp] = (((unsigned long long)wmax) << 32)
                                   | (unsigned long long)(0xFFFFFFFFu - (unsigned)p);
            }
        }
        if (valid)
            g_pack[b * NP + p] = (__float_as_uint(bestv) & 0xFFFFFFF0u) | (unsigned)bestm;
        __syncthreads();

        if (tid < NM) {
            unsigned long long best = swarp[tid][0];
            #pragma unroll
            for (int w = 1; w < 4; w++)
                if (swarp[tid][w] > best) best = swarp[tid][w];
            if (best) atomicMax(&g_best[b * NM + tid], best);
        }

        // ---- positive contributions (rare): online logsumexp, ~4 regs, no 21-array ----
        float possum = 0.0f, locsum = 0.0f;
        int cnt = 0;
        if (valid && !(bestv < 0.5f)) {
            int L = slab[bestm];                  // >= 1
            const float* s = scores + ((size_t)b * NP + p) * NC;
            float mx = __ldg(&s[0]);
            float se = 1.0f;
            float svL = 0.0f;
            for (int c = 1; c < NC; c++) {
                float v = __ldg(&s[c]);
                if (c == L) svL = v;
                if (v > mx) { se = se * __expf(mx - v) + 1.0f; mx = v; }
                else se += __expf(v - mx);
            }
            possum = mx + __logf(se) - svL;       // lse - sv[L]
            locsum = loc_l1(sbox[bestm], pr, __ldg(&plocs[b * NP + p]));
            cnt = 1;
        }
        #pragma unroll
        for (int o = 16; o; o >>= 1) {
            locsum += __shfl_down_sync(0xFFFFFFFFu, locsum, o);
            possum += __shfl_down_sync(0xFFFFFFFFu, possum, o);
            cnt    += __shfl_down_sync(0xFFFFFFFFu, cnt, o);
        }
        if (lane == 0) { rl[warp] = locsum; rp[warp] = possum; rc[warp] = cnt; }
        __syncthreads();
        if (tid == 0) {
            float L = rl[0] + rl[1] + rl[2] + rl[3];
            float Q = rp[0] + rp[1] + rp[2] + rp[3];
            int cc = rc[0] + rc[1] + rc[2] + rc[3];
            if (L != 0.0f) atomicAdd(&g_loc_sum, (double)L);
            if (Q != 0.0f) atomicAdd(&g_pos_sum, (double)Q);
            if (cc) {
                atomicAdd(&g_npos[b], cc);
                atomicAdd(&g_npos_total, cc);
            }
        }
        __syncthreads();
        pdl_trigger();
    }
}

// ================= fixup: force-assign deltas, one warp per row (R7-proven shape) =================
__global__ void fixup_kernel(
        const float4* __restrict__ plocs,
        const float*  __restrict__ scores,
        const float4* __restrict__ boxes,
        const int*    __restrict__ labels,
        const float4* __restrict__ priors) {
    pdl_wait();             // K1's pack/confneg/g_best/npos writes visible
    int b = blockIdx.x;
    int lane = threadIdx.x;

    int fp = 0;
    if (lane < NM) {
        unsigned long long kb = atomicExch(&g_best[b * NM + lane], 0ull);
        fp = (kb == 0ull) ? 0
           : (int)(0xFFFFFFFFu - (unsigned)(kb & 0xFFFFFFFFull));
    }
    bool active = (lane < NM);
    #pragma unroll
    for (int o = 0; o < NM; o++) {            // dedupe: last m wins (scatter semantics)
        int po = __shfl_sync(0xFFFFFFFFu, fp, o);
        if (o > lane && po == fp) active = false;
    }

    float d_loc = 0.0f, d_pos = 0.0f;
    int d_np = 0;
    if (active) {
        unsigned pk = g_pack[b * NP + fp];
        float bv = __uint_as_float(pk & 0xFFFFFFF0u);
        int bm = (int)(pk & 0xFu);
        int label_old = (bv < 0.5f) ? 0 : labels[b * NM + bm];
        int label_new = labels[b * NM + lane];    // >= 1
        float4 fpr = __ldg(&priors[fp]);
        float4 pl  = __ldg(&plocs[b * NP + fp]);
        float loc_new = loc_l1(__ldg(&boxes[b * NM + lane]), fpr, pl);
        const float* s = scores + (size_t)(b * NP + fp) * NC;
        if (label_old != 0) {
            // K1 counted lse - sv[label_old] and loc(bm); swap label + object (lse cancels)
            d_pos = __ldg(&s[label_old]) - __ldg(&s[label_new]);
            d_loc = loc_new - loc_l1(__ldg(&boxes[b * NM + bm]), fpr, pl);
        } else {
            float conf0 = g_confneg[b * NP + fp];
            d_pos = conf0 + __ldg(&s[0]) - __ldg(&s[label_new]);   // = lse - sv[label_new]
            d_loc = loc_new;
            d_np = 1;
            g_confneg[b * NP + fp] = 0.0f;        // leaves the negative pool
        }
    }

    #pragma unroll
    for (int o = 16; o; o >>= 1) {
        d_loc += __shfl_down_sync(0xFFFFFFFFu, d_loc, o);
        d_pos += __shfl_down_sync(0xFFFFFFFFu, d_pos, o);
        d_np  += __shfl_down_sync(0xFFFFFFFFu, d_np, o);
    }
    if (lane == 0) {
        if (d_loc != 0.0f) atomicAdd(&g_loc_sum, (double)d_loc);
        if (d_pos != 0.0f) atomicAdd(&g_pos_sum, (double)d_pos);
        if (d_np) {
            atomicAdd(&g_npos[b], d_np);
            atomicAdd(&g_npos_total, d_np);
        }
    }
    __syncwarp();
    pdl_trigger();
}

// ---------------- find_bucket: kth largest bucket (batched-load scan, warp 0 only) ----------------
template <int NBK>
__device__ __forceinline__ void find_bucket(const int* hist, int k, int lane, int* fb) {
    const int chunk = NBK >> 5;
    int base = lane * chunk;
    int cs = 0;
    #pragma unroll
    for (int i = 0; i < chunk; i++) cs += hist[base + i];
    int incl = cs;
    #pragma unroll
    for (int o = 1; o < 32; o <<= 1) {
        int t = __shfl_down_sync(0xFFFFFFFFu, incl, o);
        if (lane + o < 32) incl += t;
    }
    int excl = incl - cs;                       // count in buckets above this chunk
    bool hit = (excl < k) && (k <= incl);
    unsigned ball = __ballot_sync(0xFFFFFFFFu, hit);
    int j = __ffs(ball) - 1;
    if (lane == j) {
        int acc = excl;
        int sel = -1, rem = 0;
        #pragma unroll
        for (int g = 0; g < chunk; g += 8) {
            int h8[8];
            #pragma unroll
            for (int t = 0; t < 8; t++) h8[t] = hist[base + chunk - 1 - (g + t)];
            #pragma unroll
            for (int t = 0; t < 8; t++) {
                if (sel < 0) {
                    int h = h8[t];
                    if (acc + h >= k) { sel = chunk - 1 - (g + t); rem = k - acc; }
                    else acc += h;
                }
            }
        }
        fb[0] = base + sel;
        fb[1] = rem;
    }
}

// ================= K2: lean hard-negative mining (register-resident) + final =================
__global__ void __launch_bounds__(1024, 1) k2_kernel(float* __restrict__ out) {
    __shared__ int hist[2048];
    __shared__ int fb[2];
    __shared__ int s_npos;
    __shared__ double sredd[32];
    __shared__ int sredi[32];

    pdl_wait();             // fixup's (and transitively K1's) writes visible
    int b = blockIdx.x;
    int tid = threadIdx.x;
    int lane = tid & 31, warp = tid >> 5;
    const unsigned* cn = (const unsigned*)g_confneg + (size_t)b * NP;
    const unsigned* gp = g_pack + (size_t)b * NP;

    for (int i = tid; i < 2048; i += 1024) hist[i] = 0;
    if (tid == 0) s_npos = atomicExch(&g_npos[b], 0);     // read + self-clean

    // one pass: load conf0, zero positives (bv >= 0.5) in the register pool
    unsigned xv[9];
    #pragma unroll
    for (int j = 0; j < 9; j++) {
        int i = tid + j * 1024;
        unsigned x = 0u;
        if (i < NP) {
            x = cn[i];
            unsigned pk = gp[i];
            if (!(__uint_as_float(pk & 0xFFFFFFF0u) < 0.5f)) x = 0u;
        }
        xv[j] = x;
    }
    __syncthreads();

    int k = 3 * s_npos;
    if (k > NP) k = NP;

    // ---- level 1: top 11 bits (sign always 0), warp-aggregated atomics ----
    #pragma unroll
    for (int j = 0; j < 8; j++) {                 // i = tid + j*1024 < 8192 <= NP: all valid
        unsigned bkt = xv[j] >> 20;
        unsigned mm = __match_any_sync(0xFFFFFFFFu, bkt);
        if ((int)(__ffs(mm) - 1) == lane) atomicAdd(&hist[bkt], __popc(mm));
    }
    if (tid + 8192 < NP) atomicAdd(&hist[xv[8] >> 20], 1);
    __syncthreads();
    if (warp == 0) find_bucket<2048>(hist, k, lane, fb);
    __syncthreads();
    unsigned B1 = (unsigned)fb[0];
    int r = fb[1];
    __syncthreads();
    for (int i = tid; i < 2048; i += 1024) hist[i] = 0;
    __syncthreads();

    // ---- level 2: next 11 bits among bucket B1 ----
    #pragma unroll
    for (int j = 0; j < 9; j++) {
        int i = tid + j * 1024;
        unsigned x = xv[j];
        if (i < NP && (x >> 20) == B1) atomicAdd(&hist[(x >> 9) & 0x7FFu], 1);
    }
    __syncthreads();
    if (warp == 0) find_bucket<2048>(hist, r, lane, fb);
    __syncthreads();
    unsigned pfx = (B1 << 11) | (unsigned)fb[0];
    int r2 = fb[1];
    __syncthreads();
    for (int i = tid; i < 512; i += 1024) hist[i] = 0;
    __syncthreads();

    // ---- level 3: low 9 bits among prefix pfx ----
    #pragma unroll
    for (int j = 0; j < 9; j++) {
        int i = tid + j * 1024;
        unsigned x = xv[j];
        if (i < NP && (x >> 9) == pfx) atomicAdd(&hist[x & 0x1FFu], 1);
    }
    __syncthreads();
    if (warp == 0) find_bucket<512>(hist, r2, lane, fb);
    __syncthreads();
    unsigned thr = (pfx << 9) | (unsigned)fb[0];  // exact kth-largest bit pattern

    // ---- exact top-k sum: strictly greater + tie copies of thr ----
    float s = 0.0f;
    int c = 0;
    #pragma unroll
    for (int j = 0; j < 9; j++) {
        int i = tid + j * 1024;
        unsigned x = xv[j];
        if (i < NP && x > thr) { s += __uint_as_float(x); c++; }
    }
    double sd = (double)s;
    #pragma unroll
    for (int o = 16; o; o >>= 1) {
        sd += __shfl_down_sync(0xFFFFFFFFu, sd, o);
        c  += __shfl_down_sync(0xFFFFFFFFu, c, o);
    }
    if (lane == 0) { sredd[warp] = sd; sredi[warp] = c; }
    __syncthreads();
    if (warp == 0) {
        double S = sredd[lane];
        int C = sredi[lane];
        #pragma unroll
        for (int o = 16; o; o >>= 1) {
            S += __shfl_down_sync(0xFFFFFFFFu, S, o);
            C += __shfl_down_sync(0xFFFFFFFFu, C, o);
        }
        if (lane == 0) {
            atomicAdd(&g_hard_sum, S + (double)(k - C) * (double)__uint_as_float(thr));
            __threadfence();
            if (atomicAdd(&g_done, 1) == NB - 1) {
                __threadfence();
                int nt = atomicAdd(&g_npos_total, 0);
                double hs = atomicAdd(&g_hard_sum, 0.0);
                double ps = atomicAdd(&g_pos_sum, 0.0);
                double ls = atomicAdd(&g_loc_sum, 0.0);
                double conf_loss = (hs + ps) / (double)nt;
                long long dd = 4LL * (long long)nt;
                if (dd < 1) dd = 1;
                out[0] = (float)(conf_loss + ls / (double)dd);
                g_npos_total = 0;
                g_loc_sum = 0.0;
                g_pos_sum = 0.0;
                g_hard_sum = 0.0;
                g_done = 0;
            }
        }
    }
}

// ---------------- launch: 3 kernels, PDL-chained ----------------
extern "C" void kernel_launch(void* const* d_in, const int* in_sizes, int n_in,
                              void* d_out, int out_size) {
    const float4* plocs  = (const float4*)d_in[0];  // [B,P,4]
    const float*  scores = (const float*)d_in[1];   // [B,P,C]
    const float4* boxes  = (const float4*)d_in[2];  // [B,M,4]
    const int*    labels = (const int*)d_in[3];     // [B,M]
    const float4* priors = (const float4*)d_in[4];  // [P,4]
    float* out = (float*)d_out;

    dim3 g1(2 * NTIL, NB);
    k1_kernel<<<g1, TBLK>>>(plocs, scores, boxes, labels, priors);

    cudaLaunchAttribute attr[1];
    attr[0].id = cudaLaunchAttributeProgrammaticStreamSerialization;
    attr[0].val.programmaticStreamSerializationAllowed = 1;

    {
        cudaLaunchConfig_t cfg = {};
        cfg.gridDim = dim3(NB);
        cfg.blockDim = dim3(32);
        cfg.attrs = attr;
        cfg.numAttrs = 1;
        cfg.stream = 0;
        cudaLaunchKernelEx(&cfg, fixup_kernel, plocs, scores, boxes, labels, priors);
    }
    {
        cudaLaunchConfig_t cfg = {};
        cfg.gridDim = dim3(NB);
        cfg.blockDim = dim3(1024);
        cfg.attrs = attr;
        cfg.numAttrs = 1;
        cfg.stream = 0;
        cudaLaunchKernelEx(&cfg, k2_kernel, out);
    }
}

// round 14
// speedup vs baseline: 1.1885x; 1.1885x over previous
#include <cuda_runtime.h>
#include <math.h>

#define NB 128
#define NP 8732
#define NM 16
#define NC 21
#define TBLK 128
#define NTIL 69           // ceil(8732/128)

// ---------------- scratch (self-cleaning; static zero-init for first run) ----------------
__device__ float    g_confneg[NB * NP];    // conf0 = lse - sv[0] (K1 CE rewrites fully)
__device__ unsigned g_pack[NB * NP];       // (bestv bits & ~0xF) | bestm (K1 match rewrites fully)
__device__ unsigned long long g_best[NB * NM];
__device__ int    g_npos[NB];
__device__ int    g_npos_total;
__device__ double g_loc_sum;
__device__ double g_pos_sum;
__device__ double g_hard_sum;
__device__ int    g_done;

// ---------------- PDL helpers ----------------
__device__ __forceinline__ void pdl_wait() {
    asm volatile("griddepcontrol.wait;" ::: "memory");
}
__device__ __forceinline__ void pdl_trigger() {
    asm volatile("griddepcontrol.launch_dependents;" ::: "memory");
}

// ---------------- numeric helpers ----------------
__device__ __forceinline__ float ce_lse(const float* sv) {
    float mx = sv[0];
    #pragma unroll
    for (int c = 1; c < NC; c++) mx = fmaxf(mx, sv[c]);
    float se = 0.0f;
    #pragma unroll
    for (int c = 0; c < NC; c++) se += __expf(sv[c] - mx);
    return __logf(se) + mx;
}

__device__ __forceinline__ float loc_l1(float4 bx, float4 pr, float4 pl) {
    float cx = 0.5f * (bx.x + bx.z);
    float cy = 0.5f * (bx.y + bx.w);
    float cw = bx.z - bx.x;
    float ch = bx.w - bx.y;
    float g0 = (cx - pr.x) * 10.0f / pr.z;
    float g1 = (cy - pr.y) * 10.0f / pr.w;
    float g2 = __logf(cw / pr.z) * 5.0f;
    float g3 = __logf(ch / pr.w) * 5.0f;
    return fabsf(pl.x - g0) + fabsf(pl.y - g1) + fabsf(pl.z - g2) + fabsf(pl.w - g3);
}

// ================= K1: block-specialized CE (x<69) + match+cheap-positives (x>=69) =================
__global__ void __launch_bounds__(TBLK) k1_kernel(
        const float4* __restrict__ plocs,
        const float*  __restrict__ scores,
        const float4* __restrict__ boxes,
        const int*    __restrict__ labels,
        const float4* __restrict__ priors) {
    __shared__ float ssc[TBLK * NC];              // CE branch (10.75 KB)
    __shared__ float4 sbox[NM];                   // match branch
    __shared__ float  sarea[NM];
    __shared__ int    slab[NM];
    __shared__ unsigned long long swarp[NM][4];
    __shared__ float  rl[4], rp[4];
    __shared__ int    rc[4];

    int b = blockIdx.y;
    int tid = threadIdx.x;
    int lane = tid & 31, warp = tid >> 5;

    if (blockIdx.x < NTIL) {
        // ---------------- CE branch: conf0 = lse - sv[0] for 128 priors ----------------
        int base = blockIdx.x * TBLK;
        int nval = NP - base; if (nval > TBLK) nval = TBLK;
        const float4* src = (const float4*)(scores + ((size_t)b * NP + base) * NC);
        int nvec = (nval * NC) >> 2;              // (nval*21) % 4 == 0, base 16B-aligned
        for (int i = tid; i < nvec; i += TBLK) {
            unsigned sa = (unsigned)__cvta_generic_to_shared(&((float4*)ssc)[i]);
            asm volatile("cp.async.cg.shared.global [%0], [%1], 16;" :: "r"(sa), "l"(src + i));
        }
        asm volatile("cp.async.commit_group;");
        asm volatile("cp.async.wait_group 0;");
        __syncthreads();
        if (tid < nval) {
            const float* sv = ssc + tid * NC;     // stride 21: conflict-free
            g_confneg[b * NP + base + tid] = ce_lse(sv) - sv[0];
        }
        __syncthreads();
        pdl_trigger();
    } else {
        // ------- match branch: IoUs, per-prior best, per-object argmax, cheap positive part -------
        int base = (blockIdx.x - NTIL) * TBLK;
        int nval = NP - base; if (nval > TBLK) nval = TBLK;

        if (tid < NM) {
            float4 bx = __ldg(&boxes[b * NM + tid]);
            sbox[tid] = bx;
            sarea[tid] = (bx.z - bx.x) * (bx.w - bx.y);
            slab[tid] = labels[b * NM + tid];
        }
        if (tid < NM * 4) ((unsigned long long*)swarp)[tid] = 0ull;
        __syncthreads();

        int p = base + tid;
        bool valid = (tid < nval);
        unsigned vmask = __ballot_sync(0xFFFFFFFFu, valid);

        float bestv = -1.0f;
        int   bestm = 0;
        float4 pr = make_float4(0.f, 0.f, 1.f, 1.f);
        if (valid) pr = __ldg(&priors[p]);
        {
            float px1 = pr.x - 0.5f * pr.z;
            float py1 = pr.y - 0.5f * pr.w;
            float px2 = pr.x + 0.5f * pr.z;
            float py2 = pr.y + 0.5f * pr.w;
            float pa  = pr.z * pr.w;
            #pragma unroll
            for (int m = 0; m < NM; m++) {
                float iou = 0.0f;
                if (valid) {
                    float4 bx = sbox[m];
                    float lx = fmaxf(bx.x, px1), ly = fmaxf(bx.y, py1);
                    float rx = fminf(bx.z, px2), ry = fminf(bx.w, py2);
                    float w = fmaxf(rx - lx, 0.0f), h = fmaxf(ry - ly, 0.0f);
                    float inter = w * h;
                    iou = __fdividef(inter, sarea[m] + pa - inter);
                }
                if (iou > bestv) { bestv = iou; bestm = m; }  // strict >: lowest m on ties

                // warp argmax over p: REDUX + ballot; winner = lowest lane = lowest p
                unsigned key = valid ? __float_as_uint(iou) : 0u;
                unsigned wmax = __reduce_max_sync(0xFFFFFFFFu, key);
                unsigned ball = __ballot_sync(0xFFFFFFFFu, key == wmax) & vmask;
                if (ball && lane == (int)(__ffs(ball) - 1))
                    swarp[m][warp] = (((unsigned long long)wmax) << 32)
                                   | (unsigned long long)(0xFFFFFFFFu - (unsigned)p);
            }
        }
        if (valid)
            g_pack[b * NP + p] = (__float_as_uint(bestv) & 0xFFFFFFF0u) | (unsigned)bestm;
        __syncthreads();

        if (tid < NM) {
            unsigned long long best = swarp[tid][0];
            #pragma unroll
            for (int w = 1; w < 4; w++)
                if (swarp[tid][w] > best) best = swarp[tid][w];
            if (best) atomicMax(&g_best[b * NM + tid], best);
        }

        // ---- positive partial (rare): sv0 - svL + loc. NO lse here (K2 adds conf0). ----
        float possum = 0.0f, locsum = 0.0f;
        int cnt = 0;
        if (valid && !(bestv < 0.5f)) {
            int L = slab[bestm];                  // >= 1
            const float* s = scores + ((size_t)b * NP + p) * NC;
            possum = __ldg(&s[0]) - __ldg(&s[L]);
            locsum = loc_l1(sbox[bestm], pr, __ldg(&plocs[b * NP + p]));
            cnt = 1;
        }
        #pragma unroll
        for (int o = 16; o; o >>= 1) {
            locsum += __shfl_down_sync(0xFFFFFFFFu, locsum, o);
            possum += __shfl_down_sync(0xFFFFFFFFu, possum, o);
            cnt    += __shfl_down_sync(0xFFFFFFFFu, cnt, o);
        }
        if (lane == 0) { rl[warp] = locsum; rp[warp] = possum; rc[warp] = cnt; }
        __syncthreads();
        if (tid == 0) {
            float L = rl[0] + rl[1] + rl[2] + rl[3];
            float Q = rp[0] + rp[1] + rp[2] + rp[3];
            int cc = rc[0] + rc[1] + rc[2] + rc[3];
            if (L != 0.0f) atomicAdd(&g_loc_sum, (double)L);
            if (Q != 0.0f) atomicAdd(&g_pos_sum, (double)Q);
            if (cc) {
                atomicAdd(&g_npos[b], cc);
                atomicAdd(&g_npos_total, cc);
            }
        }
        __syncthreads();
        pdl_trigger();
    }
}

// ================= fixup: force-assign deltas, one warp per row (R13-verbatim) =================
__global__ void fixup_kernel(
        const float4* __restrict__ plocs,
        const float*  __restrict__ scores,
        const float4* __restrict__ boxes,
        const int*    __restrict__ labels,
        const float4* __restrict__ priors) {
    pdl_wait();             // K1's pack/confneg/g_best/npos writes visible
    int b = blockIdx.x;
    int lane = threadIdx.x;

    int fp = 0;
    if (lane < NM) {
        unsigned long long kb = atomicExch(&g_best[b * NM + lane], 0ull);
        fp = (kb == 0ull) ? 0
           : (int)(0xFFFFFFFFu - (unsigned)(kb & 0xFFFFFFFFull));
    }
    bool active = (lane < NM);
    #pragma unroll
    for (int o = 0; o < NM; o++) {            // dedupe: last m wins (scatter semantics)
        int po = __shfl_sync(0xFFFFFFFFu, fp, o);
        if (o > lane && po == fp) active = false;
    }

    float d_loc = 0.0f, d_pos = 0.0f;
    int d_np = 0;
    if (active) {
        unsigned pk = g_pack[b * NP + fp];
        float bv = __uint_as_float(pk & 0xFFFFFFF0u);
        int bm = (int)(pk & 0xFu);
        int label_old = (bv < 0.5f) ? 0 : labels[b * NM + bm];
        int label_new = labels[b * NM + lane];    // >= 1
        float4 fpr = __ldg(&priors[fp]);
        float4 pl  = __ldg(&plocs[b * NP + fp]);
        float loc_new = loc_l1(__ldg(&boxes[b * NM + lane]), fpr, pl);
        const float* s = scores + (size_t)(b * NP + fp) * NC;
        if (label_old != 0) {
            // K1+K2 count conf0+sv0-sv[label_old] and loc(bm); swap label + object
            d_pos = __ldg(&s[label_old]) - __ldg(&s[label_new]);
            d_loc = loc_new - loc_l1(__ldg(&boxes[b * NM + bm]), fpr, pl);
        } else {
            float conf0 = g_confneg[b * NP + fp];
            d_pos = conf0 + __ldg(&s[0]) - __ldg(&s[label_new]);   // = lse - sv[label_new]
            d_loc = loc_new;
            d_np = 1;
            g_confneg[b * NP + fp] = 0.0f;        // leaves the negative pool (pack stays negative)
        }
    }

    #pragma unroll
    for (int o = 16; o; o >>= 1) {
        d_loc += __shfl_down_sync(0xFFFFFFFFu, d_loc, o);
        d_pos += __shfl_down_sync(0xFFFFFFFFu, d_pos, o);
        d_np  += __shfl_down_sync(0xFFFFFFFFu, d_np, o);
    }
    if (lane == 0) {
        if (d_loc != 0.0f) atomicAdd(&g_loc_sum, (double)d_loc);
        if (d_pos != 0.0f) atomicAdd(&g_pos_sum, (double)d_pos);
        if (d_np) {
            atomicAdd(&g_npos[b], d_np);
            atomicAdd(&g_npos_total, d_np);
        }
    }
    __syncwarp();
    pdl_trigger();
}

// ---------------- find_bucket: kth largest bucket (batched-load scan, warp 0 only) ----------------
template <int NBK>
__device__ __forceinline__ void find_bucket(const int* hist, int k, int lane, int* fb) {
    const int chunk = NBK >> 5;
    int base = lane * chunk;
    int cs = 0;
    #pragma unroll
    for (int i = 0; i < chunk; i++) cs += hist[base + i];
    int incl = cs;
    #pragma unroll
    for (int o = 1; o < 32; o <<= 1) {
        int t = __shfl_down_sync(0xFFFFFFFFu, incl, o);
        if (lane + o < 32) incl += t;
    }
    int excl = incl - cs;                       // count in buckets above this chunk
    bool hit = (excl < k) && (k <= incl);
    unsigned ball = __ballot_sync(0xFFFFFFFFu, hit);
    int j = __ffs(ball) - 1;
    if (lane == j) {
        int acc = excl;
        int sel = -1, rem = 0;
        #pragma unroll
        for (int g = 0; g < chunk; g += 8) {
            int h8[8];
            #pragma unroll
            for (int t = 0; t < 8; t++) h8[t] = hist[base + chunk - 1 - (g + t)];
            #pragma unroll
            for (int t = 0; t < 8; t++) {
                if (sel < 0) {
                    int h = h8[t];
                    if (acc + h >= k) { sel = chunk - 1 - (g + t); rem = k - acc; }
                    else acc += h;
                }
            }
        }
        fb[0] = base + sel;
        fb[1] = rem;
    }
}

// ================= K2: lean hardneg + Σ_pos conf0 + final (register-resident) =================
__global__ void __launch_bounds__(1024, 1) k2_kernel(float* __restrict__ out) {
    __shared__ int hist[2048];
    __shared__ int fb[2];
    __shared__ int s_npos;
    __shared__ double sredd[32];
    __shared__ int sredi[32];

    pdl_wait();             // fixup's (and transitively K1's) writes visible
    int b = blockIdx.x;
    int tid = threadIdx.x;
    int lane = tid & 31, warp = tid >> 5;
    const unsigned* cn = (const unsigned*)g_confneg + (size_t)b * NP;
    const unsigned* gp = g_pack + (size_t)b * NP;

    for (int i = tid; i < 2048; i += 1024) hist[i] = 0;
    if (tid == 0) s_npos = atomicExch(&g_npos[b], 0);     // read + self-clean

    // one pass: load conf0; for pack-positives accumulate conf0 then zero from pool
    unsigned xv[9];
    float pconf = 0.0f;
    #pragma unroll
    for (int j = 0; j < 9; j++) {
        int i = tid + j * 1024;
        unsigned x = 0u;
        if (i < NP) {
            x = cn[i];
            unsigned pk = gp[i];
            if (!(__uint_as_float(pk & 0xFFFFFFF0u) < 0.5f)) {
                pconf += __uint_as_float(x);      // Σ_pos conf0 (K1 counted sv0-svL part)
                x = 0u;
            }
        }
        xv[j] = x;
    }
    // reduce Σ_pos conf0
    #pragma unroll
    for (int o = 16; o; o >>= 1)
        pconf += __shfl_down_sync(0xFFFFFFFFu, pconf, o);
    if (lane == 0) sredd[warp] = (double)pconf;
    __syncthreads();
    if (tid == 0) {
        double P = 0.0;
        #pragma unroll
        for (int w = 0; w < 32; w++) P += sredd[w];
        if (P != 0.0) atomicAdd(&g_pos_sum, P);
    }
    __syncthreads();

    int k = 3 * s_npos;
    if (k > NP) k = NP;

    // ---- level 1: top 11 bits (sign always 0), warp-aggregated atomics ----
    #pragma unroll
    for (int j = 0; j < 8; j++) {                 // i = tid + j*1024 < 8192 <= NP: all valid
        unsigned bkt = xv[j] >> 20;
        unsigned mm = __match_any_sync(0xFFFFFFFFu, bkt);
        if ((int)(__ffs(mm) - 1) == lane) atomicAdd(&hist[bkt], __popc(mm));
    }
    if (tid + 8192 < NP) atomicAdd(&hist[xv[8] >> 20], 1);
    __syncthreads();
    if (warp == 0) find_bucket<2048>(hist, k, lane, fb);
    __syncthreads();
    unsigned B1 = (unsigned)fb[0];
    int r = fb[1];
    __syncthreads();
    for (int i = tid; i < 2048; i += 1024) hist[i] = 0;
    __syncthreads();

    // ---- level 2: next 11 bits among bucket B1 ----
    #pragma unroll
    for (int j = 0; j < 9; j++) {
        int i = tid + j * 1024;
        unsigned x = xv[j];
        if (i < NP && (x >> 20) == B1) atomicAdd(&hist[(x >> 9) & 0x7FFu], 1);
    }
    __syncthreads();
    if (warp == 0) find_bucket<2048>(hist, r, lane, fb);
    __syncthreads();
    unsigned pfx = (B1 << 11) | (unsigned)fb[0];
    int r2 = fb[1];
    __syncthreads();
    for (int i = tid; i < 512; i += 1024) hist[i] = 0;
    __syncthreads();

    // ---- level 3: low 9 bits among prefix pfx ----
    #pragma unroll
    for (int j = 0; j < 9; j++) {
        int i = tid + j * 1024;
        unsigned x = xv[j];
        if (i < NP && (x >> 9) == pfx) atomicAdd(&hist[x & 0x1FFu], 1);
    }
    __syncthreads();
    if (warp == 0) find_bucket<512>(hist, r2, lane, fb);
    __syncthreads();
    unsigned thr = (pfx << 9) | (unsigned)fb[0];  // exact kth-largest bit pattern

    // ---- exact top-k sum: strictly greater + tie copies of thr ----
    float s = 0.0f;
    int c = 0;
    #pragma unroll
    for (int j = 0; j < 9; j++) {
        int i = tid + j * 1024;
        unsigned x = xv[j];
        if (i < NP && x > thr) { s += __uint_as_float(x); c++; }
    }
    double sd = (double)s;
    #pragma unroll
    for (int o = 16; o; o >>= 1) {
        sd += __shfl_down_sync(0xFFFFFFFFu, sd, o);
        c  += __shfl_down_sync(0xFFFFFFFFu, c, o);
    }
    if (lane == 0) { sredd[warp] = sd; sredi[warp] = c; }
    __syncthreads();
    if (warp == 0) {
        double S = sredd[lane];
        int C = sredi[lane];
        #pragma unroll
        for (int o = 16; o; o >>= 1) {
            S += __shfl_down_sync(0xFFFFFFFFu, S, o);
            C += __shfl_down_sync(0xFFFFFFFFu, C, o);
        }
        if (lane == 0) {
            atomicAdd(&g_hard_sum, S + (double)(k - C) * (double)__uint_as_float(thr));
            __threadfence();
            if (atomicAdd(&g_done, 1) == NB - 1) {
                __threadfence();
                int nt = atomicAdd(&g_npos_total, 0);
                double hs = atomicAdd(&g_hard_sum, 0.0);
                double ps = atomicAdd(&g_pos_sum, 0.0);
                double ls = atomicAdd(&g_loc_sum, 0.0);
                double conf_loss = (hs + ps) / (double)nt;
                long long dd = 4LL * (long long)nt;
                if (dd < 1) dd = 1;
                out[0] = (float)(conf_loss + ls / (double)dd);
                g_npos_total = 0;
                g_loc_sum = 0.0;
                g_pos_sum = 0.0;
                g_hard_sum = 0.0;
                g_done = 0;
            }
        }
    }
}

// ---------------- launch: 3 kernels, PDL-chained ----------------
extern "C" void kernel_launch(void* const* d_in, const int* in_sizes, int n_in,
                              void* d_out, int out_size) {
    const float4* plocs  = (const float4*)d_in[0];  // [B,P,4]
    const float*  scores = (const float*)d_in[1];   // [B,P,C]
    const float4* boxes  = (const float4*)d_in[2];  // [B,M,4]
    const int*    labels = (const int*)d_in[3];     // [B,M]
    const float4* priors = (const float4*)d_in[4];  // [P,4]
    float* out = (float*)d_out;

    dim3 g1(2 * NTIL, NB);
    k1_kernel<<<g1, TBLK>>>(plocs, scores, boxes, labels, priors);

    cudaLaunchAttribute attr[1];
    attr[0].id = cudaLaunchAttributeProgrammaticStreamSerialization;
    attr[0].val.programmaticStreamSerializationAllowed = 1;

    {
        cudaLaunchConfig_t cfg = {};
        cfg.gridDim = dim3(NB);
        cfg.blockDim = dim3(32);
        cfg.attrs = attr;
        cfg.numAttrs = 1;
        cfg.stream = 0;
        cudaLaunchKernelEx(&cfg, fixup_kernel, plocs, scores, boxes, labels, priors);
    }
    {
        cudaLaunchConfig_t cfg = {};
        cfg.gridDim = dim3(NB);
        cfg.blockDim = dim3(1024);
        cfg.attrs = attr;
        cfg.numAttrs = 1;
        cfg.stream = 0;
        cudaLaunchKernelEx(&cfg, k2_kernel, out);
    }
}

// round 15
// speedup vs baseline: 1.2262x; 1.0317x over previous
#include <cuda_runtime.h>
#include <math.h>

#define NB 128
#define NP 8732
#define NM 16
#define NC 21
#define TBLK 128
#define NTIL_CE 69        // ceil(8732/128)
#define NTIL_M  35        // ceil(8732/256)
#define MBLK 256          // priors per match block

// ---------------- scratch (self-cleaning; static zero-init for first run) ----------------
__device__ float    g_confneg[NB * NP];    // conf0 = lse - sv[0] (K1 CE rewrites fully)
__device__ unsigned g_pack[NB * NP];       // (bestv bits & ~0xF) | bestm (K1 match rewrites fully)
__device__ unsigned long long g_best[NB * NM];
__device__ int    g_npos[NB];
__device__ int    g_npos_total;
__device__ double g_loc_sum;
__device__ double g_pos_sum;
__device__ double g_hard_sum;
__device__ int    g_done;

// ---------------- PDL helpers ----------------
__device__ __forceinline__ void pdl_wait() {
    asm volatile("griddepcontrol.wait;" ::: "memory");
}
__device__ __forceinline__ void pdl_trigger() {
    asm volatile("griddepcontrol.launch_dependents;" ::: "memory");
}

// ---------------- numeric helpers ----------------
__device__ __forceinline__ float ce_lse(const float* sv) {
    float mx = sv[0];
    #pragma unroll
    for (int c = 1; c < NC; c++) mx = fmaxf(mx, sv[c]);
    float se = 0.0f;
    #pragma unroll
    for (int c = 0; c < NC; c++) se += __expf(sv[c] - mx);
    return __logf(se) + mx;
}

__device__ __forceinline__ float loc_l1(float4 bx, float4 pr, float4 pl) {
    float cx = 0.5f * (bx.x + bx.z);
    float cy = 0.5f * (bx.y + bx.w);
    float cw = bx.z - bx.x;
    float ch = bx.w - bx.y;
    float g0 = (cx - pr.x) * 10.0f / pr.z;
    float g1 = (cy - pr.y) * 10.0f / pr.w;
    float g2 = __logf(cw / pr.z) * 5.0f;
    float g3 = __logf(ch / pr.w) * 5.0f;
    return fabsf(pl.x - g0) + fabsf(pl.y - g1) + fabsf(pl.z - g2) + fabsf(pl.w - g3);
}

__device__ __forceinline__ float iou_calc(float4 bx, float sa,
                                          float px1, float py1, float px2, float py2,
                                          float pa, bool valid) {
    if (!valid) return 0.0f;
    float lx = fmaxf(bx.x, px1), ly = fmaxf(bx.y, py1);
    float rx = fminf(bx.z, px2), ry = fminf(bx.w, py2);
    float w = fmaxf(rx - lx, 0.0f), h = fmaxf(ry - ly, 0.0f);
    float inter = w * h;
    return __fdividef(inter, sa + pa - inter);
}

// ================= K1: block-specialized CE (x<69) + match 256-priors/block (x>=69) =================
__global__ void __launch_bounds__(TBLK) k1_kernel(
        const float4* __restrict__ plocs,
        const float*  __restrict__ scores,
        const float4* __restrict__ boxes,
        const int*    __restrict__ labels,
        const float4* __restrict__ priors) {
    __shared__ float ssc[TBLK * NC];              // CE branch (10.75 KB)
    __shared__ float4 sbox[NM];                   // match branch
    __shared__ float  sarea[NM];
    __shared__ int    slab[NM];
    __shared__ unsigned long long swarp[NM][4];
    __shared__ float  rl[4], rp[4];
    __shared__ int    rc[4];

    int b = blockIdx.y;
    int tid = threadIdx.x;
    int lane = tid & 31, warp = tid >> 5;

    if (blockIdx.x < NTIL_CE) {
        // ---------------- CE branch: conf0 = lse - sv[0] for 128 priors ----------------
        int base = blockIdx.x * TBLK;
        int nval = NP - base; if (nval > TBLK) nval = TBLK;
        const float4* src = (const float4*)(scores + ((size_t)b * NP + base) * NC);
        int nvec = (nval * NC) >> 2;              // (nval*21) % 4 == 0, base 16B-aligned
        for (int i = tid; i < nvec; i += TBLK) {
            unsigned sa = (unsigned)__cvta_generic_to_shared(&((float4*)ssc)[i]);
            asm volatile("cp.async.cg.shared.global [%0], [%1], 16;" :: "r"(sa), "l"(src + i));
        }
        asm volatile("cp.async.commit_group;");
        asm volatile("cp.async.wait_group 0;");
        __syncthreads();
        if (tid < nval) {
            const float* sv = ssc + tid * NC;     // stride 21: conflict-free
            g_confneg[b * NP + base + tid] = ce_lse(sv) - sv[0];
        }
        __syncthreads();
        pdl_trigger();
    } else {
        // ------- match branch: 2 priors/thread; IoUs, argmaxes, cheap positive part -------
        int base = (blockIdx.x - NTIL_CE) * MBLK;
        int p0 = base + tid;
        int p1 = base + TBLK + tid;
        bool v0 = (p0 < NP);
        bool v1 = (p1 < NP);

        if (tid < NM) {
            float4 bx = __ldg(&boxes[b * NM + tid]);
            sbox[tid] = bx;
            sarea[tid] = (bx.z - bx.x) * (bx.w - bx.y);
            slab[tid] = labels[b * NM + tid];
        }
        if (tid < NM * 4) ((unsigned long long*)swarp)[tid] = 0ull;
        __syncthreads();

        float4 pr0 = make_float4(0.f, 0.f, 1.f, 1.f);
        float4 pr1 = make_float4(0.f, 0.f, 1.f, 1.f);
        if (v0) pr0 = __ldg(&priors[p0]);
        if (v1) pr1 = __ldg(&priors[p1]);

        float a_x1 = pr0.x - 0.5f * pr0.z, a_y1 = pr0.y - 0.5f * pr0.w;
        float a_x2 = pr0.x + 0.5f * pr0.z, a_y2 = pr0.y + 0.5f * pr0.w;
        float a_pa = pr0.z * pr0.w;
        float c_x1 = pr1.x - 0.5f * pr1.z, c_y1 = pr1.y - 0.5f * pr1.w;
        float c_x2 = pr1.x + 0.5f * pr1.z, c_y2 = pr1.y + 0.5f * pr1.w;
        float c_pa = pr1.z * pr1.w;

        float bestv0 = -1.0f, bestv1 = -1.0f;
        int   bestm0 = 0, bestm1 = 0;

        #pragma unroll
        for (int m = 0; m < NM; m++) {
            float4 bx = sbox[m];
            float sa = sarea[m];
            float iou0 = iou_calc(bx, sa, a_x1, a_y1, a_x2, a_y2, a_pa, v0);
            float iou1 = iou_calc(bx, sa, c_x1, c_y1, c_x2, c_y2, c_pa, v1);
            if (iou0 > bestv0) { bestv0 = iou0; bestm0 = m; }  // strict >: lowest m
            if (iou1 > bestv1) { bestv1 = iou1; bestm1 = m; }

            unsigned k0 = v0 ? __float_as_uint(iou0) : 0u;
            unsigned k1 = v1 ? __float_as_uint(iou1) : 0u;
            unsigned mx2 = k0 > k1 ? k0 : k1;
            unsigned wmax = __reduce_max_sync(0xFFFFFFFFu, mx2);
            if (wmax) {   // warp-uniform
                unsigned b0 = __ballot_sync(0xFFFFFFFFu, k0 == wmax);
                unsigned b1 = __ballot_sync(0xFFFFFFFFu, k1 == wmax);
                // all p0 < all p1 -> ties resolve to lowest p via b0-first, lowest lane
                int winlane = b0 ? (__ffs(b0) - 1) : (__ffs(b1) - 1);
                int p_win = b0 ? (base + (warp << 5) + winlane)
                               : (base + TBLK + (warp << 5) + winlane);
                if (lane == winlane)
                    swarp[m][warp] = (((unsigned long long)wmax) << 32)
                                   | (unsigned long long)(0xFFFFFFFFu - (unsigned)p_win);
            }
        }
        if (v0)
            g_pack[b * NP + p0] = (__float_as_uint(bestv0) & 0xFFFFFFF0u) | (unsigned)bestm0;
        if (v1)
            g_pack[b * NP + p1] = (__float_as_uint(bestv1) & 0xFFFFFFF0u) | (unsigned)bestm1;
        __syncthreads();

        if (tid < NM) {
            unsigned long long best = swarp[tid][0];
            #pragma unroll
            for (int w = 1; w < 4; w++)
                if (swarp[tid][w] > best) best = swarp[tid][w];
            if (best) atomicMax(&g_best[b * NM + tid], best);
        }

        // ---- positive partial (rare): sv0 - svL + loc. NO lse here (K2 adds conf0). ----
        float possum = 0.0f, locsum = 0.0f;
        int cnt = 0;
        if (v0 && !(bestv0 < 0.5f)) {
            int L = slab[bestm0];
            const float* s = scores + ((size_t)b * NP + p0) * NC;
            possum += __ldg(&s[0]) - __ldg(&s[L]);
            locsum += loc_l1(sbox[bestm0], pr0, __ldg(&plocs[b * NP + p0]));
            cnt++;
        }
        if (v1 && !(bestv1 < 0.5f)) {
            int L = slab[bestm1];
            const float* s = scores + ((size_t)b * NP + p1) * NC;
            possum += __ldg(&s[0]) - __ldg(&s[L]);
            locsum += loc_l1(sbox[bestm1], pr1, __ldg(&plocs[b * NP + p1]));
            cnt++;
        }
        #pragma unroll
        for (int o = 16; o; o >>= 1) {
            locsum += __shfl_down_sync(0xFFFFFFFFu, locsum, o);
            possum += __shfl_down_sync(0xFFFFFFFFu, possum, o);
            cnt    += __shfl_down_sync(0xFFFFFFFFu, cnt, o);
        }
        if (lane == 0) { rl[warp] = locsum; rp[warp] = possum; rc[warp] = cnt; }
        __syncthreads();
        if (tid == 0) {
            float L = rl[0] + rl[1] + rl[2] + rl[3];
            float Q = rp[0] + rp[1] + rp[2] + rp[3];
            int cc = rc[0] + rc[1] + rc[2] + rc[3];
            if (L != 0.0f) atomicAdd(&g_loc_sum, (double)L);
            if (Q != 0.0f) atomicAdd(&g_pos_sum, (double)Q);
            if (cc) {
                atomicAdd(&g_npos[b], cc);
                atomicAdd(&g_npos_total, cc);
            }
        }
        __syncthreads();
        pdl_trigger();
    }
}

// ---------------- find_bucket: kth largest bucket (batched-load scan, warp 0 only) ----------------
template <int NBK>
__device__ __forceinline__ void find_bucket(const int* hist, int k, int lane, int* fb) {
    const int chunk = NBK >> 5;
    int base = lane * chunk;
    int cs = 0;
    #pragma unroll
    for (int i = 0; i < chunk; i++) cs += hist[base + i];
    int incl = cs;
    #pragma unroll
    for (int o = 1; o < 32; o <<= 1) {
        int t = __shfl_down_sync(0xFFFFFFFFu, incl, o);
        if (lane + o < 32) incl += t;
    }
    int excl = incl - cs;                       // count in buckets above this chunk
    bool hit = (excl < k) && (k <= incl);
    unsigned ball = __ballot_sync(0xFFFFFFFFu, hit);
    int j = __ffs(ball) - 1;
    if (lane == j) {
        int acc = excl;
        int sel = -1, rem = 0;
        #pragma unroll
        for (int g = 0; g < chunk; g += 8) {
            int h8[8];
            #pragma unroll
            for (int t = 0; t < 8; t++) h8[t] = hist[base + chunk - 1 - (g + t)];
            #pragma unroll
            for (int t = 0; t < 8; t++) {
                if (sel < 0) {
                    int h = h8[t];
                    if (acc + h >= k) { sel = chunk - 1 - (g + t); rem = k - acc; }
                    else acc += h;
                }
            }
        }
        fb[0] = base + sel;
        fb[1] = rem;
    }
}

// ================= K2: fixup (warp0) + Σ_pos conf0 + hardneg + final =================
__global__ void __launch_bounds__(1024, 1) k2_kernel(
        const float4* __restrict__ plocs,
        const float*  __restrict__ scores,
        const float4* __restrict__ boxes,
        const int*    __restrict__ labels,
        const float4* __restrict__ priors,
        float* __restrict__ out) {
    __shared__ int hist[2048];
    __shared__ int fb[2];
    __shared__ int s_npos;
    __shared__ int s_flist[NM];
    __shared__ int s_fcnt;
    __shared__ double sredd[32];
    __shared__ int sredi[32];

    pdl_wait();             // K1's pack/confneg/g_best/npos writes visible
    int b = blockIdx.x;
    int tid = threadIdx.x;
    int lane = tid & 31, warp = tid >> 5;
    const unsigned* cn = (const unsigned*)g_confneg + (size_t)b * NP;
    const unsigned* gp = g_pack + (size_t)b * NP;

    unsigned xv[9];
    float pconf = 0.0f;

    if (warp == 0) {
        // ---- fixup: lean force-assign deltas (no sv[] array -> no spill) ----
        int fp = 0;
        if (lane < NM) {
            unsigned long long kb = atomicExch(&g_best[b * NM + lane], 0ull);
            fp = (kb == 0ull) ? 0
               : (int)(0xFFFFFFFFu - (unsigned)(kb & 0xFFFFFFFFull));
        }
        bool active = (lane < NM);
        #pragma unroll
        for (int o = 0; o < NM; o++) {            // dedupe: last m wins (scatter semantics)
            int po = __shfl_sync(0xFFFFFFFFu, fp, o);
            if (o > lane && po == fp) active = false;
        }
        float d_loc = 0.0f, d_pos = 0.0f;
        int d_np = 0;
        if (active) {
            unsigned pk = gp[fp];
            float bv = __uint_as_float(pk & 0xFFFFFFF0u);
            int bm = (int)(pk & 0xFu);
            int label_old = (bv < 0.5f) ? 0 : labels[b * NM + bm];
            int label_new = labels[b * NM + lane];    // >= 1
            float4 fpr = __ldg(&priors[fp]);
            float4 pl  = __ldg(&plocs[b * NP + fp]);
            float loc_new = loc_l1(__ldg(&boxes[b * NM + lane]), fpr, pl);
            const float* s = scores + (size_t)(b * NP + fp) * NC;
            if (label_old != 0) {
                // K1+pconf count conf0+sv0-sv[label_old] and loc(bm); swap label + object
                d_pos = __ldg(&s[label_old]) - __ldg(&s[label_new]);
                d_loc = loc_new - loc_l1(__ldg(&boxes[b * NM + bm]), fpr, pl);
            } else {
                float conf0 = __uint_as_float(cn[fp]);
                d_pos = conf0 + __ldg(&s[0]) - __ldg(&s[label_new]);
                d_loc = loc_new;
                d_np = 1;    // new positive: patch out of xv below (pack stays negative)
            }
        }
        unsigned fm = __ballot_sync(0xFFFFFFFFu, d_np != 0);
        if (d_np) s_flist[__popc(fm & ((1u << lane) - 1))] = fp;
        float rloc = d_loc, rpos = d_pos;
        int rnp = d_np;
        #pragma unroll
        for (int o = 16; o; o >>= 1) {
            rloc += __shfl_down_sync(0xFFFFFFFFu, rloc, o);
            rpos += __shfl_down_sync(0xFFFFFFFFu, rpos, o);
            rnp  += __shfl_down_sync(0xFFFFFFFFu, rnp, o);
        }
        if (lane == 0) {
            s_fcnt = __popc(fm);
            if (rloc != 0.0f) atomicAdd(&g_loc_sum, (double)rloc);
            if (rpos != 0.0f) atomicAdd(&g_pos_sum, (double)rpos);
            if (rnp) atomicAdd(&g_npos_total, rnp);
            s_npos = atomicExch(&g_npos[b], 0) + rnp;   // read + self-clean
        }
        // warp 0 loads its xv slots after fixup
        #pragma unroll
        for (int j = 0; j < 9; j++) {
            int i = tid + j * 1024;
            unsigned x = 0u;
            if (i < NP) {
                x = cn[i];
                if (!(__uint_as_float(gp[i] & 0xFFFFFFF0u) < 0.5f)) {
                    pconf += __uint_as_float(x);
                    x = 0u;
                }
            }
            xv[j] = x;
        }
    } else {
        // warps 1..31: zero hist + load xv with pconf (overlaps fixup)
        for (int i = tid - 32; i < 2048; i += 992) hist[i] = 0;
        #pragma unroll
        for (int j = 0; j < 9; j++) {
            int i = tid + j * 1024;
            unsigned x = 0u;
            if (i < NP) {
                x = cn[i];
                if (!(__uint_as_float(gp[i] & 0xFFFFFFF0u) < 0.5f)) {
                    pconf += __uint_as_float(x);
                    x = 0u;
                }
            }
            xv[j] = x;
        }
    }
    __syncthreads();

    // patch forced new-positives out of the register-resident negative pool
    {
        int fcnt = s_fcnt;
        for (int e = 0; e < fcnt; e++) {
            int fp = s_flist[e];
            if ((fp & 1023) == tid) xv[fp >> 10] = 0u;
        }
    }

    // reduce Σ_pos conf0
    #pragma unroll
    for (int o = 16; o; o >>= 1)
        pconf += __shfl_down_sync(0xFFFFFFFFu, pconf, o);
    if (lane == 0) sredd[warp] = (double)pconf;
    __syncthreads();
    if (tid == 0) {
        double P = 0.0;
        #pragma unroll
        for (int w = 0; w < 32; w++) P += sredd[w];
        if (P != 0.0) atomicAdd(&g_pos_sum, P);
    }
    __syncthreads();

    int k = 3 * s_npos;
    if (k > NP) k = NP;

    // ---- level 1: top 11 bits (sign always 0), warp-aggregated atomics ----
    #pragma unroll
    for (int j = 0; j < 8; j++) {                 // i = tid + j*1024 < 8192 <= NP: all valid
        unsigned bkt = xv[j] >> 20;
        unsigned mm = __match_any_sync(0xFFFFFFFFu, bkt);
        if ((int)(__ffs(mm) - 1) == lane) atomicAdd(&hist[bkt], __popc(mm));
    }
    if (tid + 8192 < NP) atomicAdd(&hist[xv[8] >> 20], 1);
    __syncthreads();
    if (warp == 0) find_bucket<2048>(hist, k, lane, fb);
    __syncthreads();
    unsigned B1 = (unsigned)fb[0];
    int r = fb[1];
    __syncthreads();
    for (int i = tid; i < 2048; i += 1024) hist[i] = 0;
    __syncthreads();

    // ---- level 2: next 11 bits among bucket B1 ----
    #pragma unroll
    for (int j = 0; j < 9; j++) {
        int i = tid + j * 1024;
        unsigned x = xv[j];
        if (i < NP && (x >> 20) == B1) atomicAdd(&hist[(x >> 9) & 0x7FFu], 1);
    }
    __syncthreads();
    if (warp == 0) find_bucket<2048>(hist, r, lane, fb);
    __syncthreads();
    unsigned pfx = (B1 << 11) | (unsigned)fb[0];
    int r2 = fb[1];
    __syncthreads();
    for (int i = tid; i < 512; i += 1024) hist[i] = 0;
    __syncthreads();

    // ---- level 3: low 9 bits among prefix pfx ----
    #pragma unroll
    for (int j = 0; j < 9; j++) {
        int i = tid + j * 1024;
        unsigned x = xv[j];
        if (i < NP && (x >> 9) == pfx) atomicAdd(&hist[x & 0x1FFu], 1);
    }
    __syncthreads();
    if (warp == 0) find_bucket<512>(hist, r2, lane, fb);
    __syncthreads();
    unsigned thr = (pfx << 9) | (unsigned)fb[0];  // exact kth-largest bit pattern

    // ---- exact top-k sum: strictly greater + tie copies of thr ----
    float s = 0.0f;
    int c = 0;
    #pragma unroll
    for (int j = 0; j < 9; j++) {
        int i = tid + j * 1024;
        unsigned x = xv[j];
        if (i < NP && x > thr) { s += __uint_as_float(x); c++; }
    }
    double sd = (double)s;
    #pragma unroll
    for (int o = 16; o; o >>= 1) {
        sd += __shfl_down_sync(0xFFFFFFFFu, sd, o);
        c  += __shfl_down_sync(0xFFFFFFFFu, c, o);
    }
    if (lane == 0) { sredd[warp] = sd; sredi[warp] = c; }
    __syncthreads();
    if (warp == 0) {
        double S = sredd[lane];
        int C = sredi[lane];
        #pragma unroll
        for (int o = 16; o; o >>= 1) {
            S += __shfl_down_sync(0xFFFFFFFFu, S, o);
            C += __shfl_down_sync(0xFFFFFFFFu, C, o);
        }
        if (lane == 0) {
            atomicAdd(&g_hard_sum, S + (double)(k - C) * (double)__uint_as_float(thr));
            __threadfence();
            if (atomicAdd(&g_done, 1) == NB - 1) {
                __threadfence();
                int nt = atomicAdd(&g_npos_total, 0);
                double hs = atomicAdd(&g_hard_sum, 0.0);
                double ps = atomicAdd(&g_pos_sum, 0.0);
                double ls = atomicAdd(&g_loc_sum, 0.0);
                double conf_loss = (hs + ps) / (double)nt;
                long long dd = 4LL * (long long)nt;
                if (dd < 1) dd = 1;
                out[0] = (float)(conf_loss + ls / (double)dd);
                g_npos_total = 0;
                g_loc_sum = 0.0;
                g_pos_sum = 0.0;
                g_hard_sum = 0.0;
                g_done = 0;
            }
        }
    }
}

// ---------------- launch: 2 kernels, PDL-chained ----------------
extern "C" void kernel_launch(void* const* d_in, const int* in_sizes, int n_in,
                              void* d_out, int out_size) {
    const float4* plocs  = (const float4*)d_in[0];  // [B,P,4]
    const float*  scores = (const float*)d_in[1];   // [B,P,C]
    const float4* boxes  = (const float4*)d_in[2];  // [B,M,4]
    const int*    labels = (const int*)d_in[3];     // [B,M]
    const float4* priors = (const float4*)d_in[4];  // [P,4]
    float* out = (float*)d_out;

    dim3 g1(NTIL_CE + NTIL_M, NB);
    k1_kernel<<<g1, TBLK>>>(plocs, scores, boxes, labels, priors);

    cudaLaunchAttribute attr[1];
    attr[0].id = cudaLaunchAttributeProgrammaticStreamSerialization;
    attr[0].val.programmaticStreamSerializationAllowed = 1;

    cudaLaunchConfig_t cfg = {};
    cfg.gridDim = dim3(NB);
    cfg.blockDim = dim3(1024);
    cfg.attrs = attr;
    cfg.numAttrs = 1;
    cfg.stream = 0;
    cudaLaunchKernelEx(&cfg, k2_kernel, plocs, scores, boxes, labels, priors, out);
}